// round 15
// baseline (speedup 1.0000x reference)
#include <cuda_runtime.h>
#include <cuda_fp16.h>
#include <cstdint>

// Problem dims
constexpr int Lt = 128;
constexpr int Bt = 128;
constexpr int Hd = 1024;
constexpr int Gd = 4 * Hd;       // 4096
constexpr int KA = 512;          // K of both sub-GEMMs

// Static scratch
__device__ float g_gx_act[(size_t)Lt * Bt * Gd];     // act-side gate projections
__device__ float g_gx_inp[(size_t)Bt * Gd];          // input-side + biases
__device__ __align__(16) __half g_act_h[(size_t)Lt * Bt * KA];
__device__ __align__(16) __half g_inp_h[(size_t)Bt * KA];
__device__ __align__(16) __half g_wih_h[(size_t)Gd * 1024];
__device__ __align__(16) __half g_hbuf_h[2][Bt * Hd];
__device__ unsigned g_bar_count;
__device__ unsigned g_bar_gen;
__device__ unsigned g_tile_ctr;                      // producer work queue
__device__ unsigned g_inp_done;                      // inp tiles finished (of 64)
__device__ unsigned g_l_cnt[Lt];                     // act tiles finished per l (of 64)

// ---------------------------------------------------------------- helpers
__device__ __forceinline__ uint32_t h2u(__half2 v) {
    __half2_raw r = *(__half2_raw*)&v;
    return (uint32_t)r.x | ((uint32_t)r.y << 16);
}
__device__ __forceinline__ void mma16(float* c, const uint32_t* a,
                                      uint32_t b0, uint32_t b1) {
    asm volatile(
        "mma.sync.aligned.m16n8k16.row.col.f32.f16.f16.f32 "
        "{%0,%1,%2,%3},{%4,%5,%6,%7},{%8,%9},{%0,%1,%2,%3};"
        : "+f"(c[0]), "+f"(c[1]), "+f"(c[2]), "+f"(c[3])
        : "r"(a[0]), "r"(a[1]), "r"(a[2]), "r"(a[3]), "r"(b0), "r"(b1));
}
__device__ __forceinline__ void ldsm4(uint32_t& d0, uint32_t& d1,
                                      uint32_t& d2, uint32_t& d3, uint32_t a) {
    asm volatile("ldmatrix.sync.aligned.m8n8.x4.shared.b16 {%0,%1,%2,%3}, [%4];"
                 : "=r"(d0), "=r"(d1), "=r"(d2), "=r"(d3) : "r"(a));
}
__device__ __forceinline__ void cpa16(uint32_t d, const void* s) {
    asm volatile("cp.async.cg.shared.global [%0], [%1], 16;" :: "r"(d), "l"(s));
}
__device__ __forceinline__ void cpcommit() { asm volatile("cp.async.commit_group;"); }
template<int N> __device__ __forceinline__ void cpwait() {
    asm volatile("cp.async.wait_group %0;" :: "n"(N));
}
__device__ __forceinline__ uint32_t s2u(const void* p) {
    return (uint32_t)__cvta_generic_to_shared(p);
}
__device__ __forceinline__ float sigm(float x) { return 1.0f / (1.0f + expf(-x)); }
__device__ __forceinline__ unsigned ldacq(const unsigned* p) {
    unsigned v;
    asm volatile("ld.acquire.gpu.global.u32 %0, [%1];" : "=r"(v) : "l"(p) : "memory");
    return v;
}
__device__ __forceinline__ void redrel(unsigned* p, unsigned v) {
    asm volatile("red.release.gpu.global.add.u32 [%0], %1;" :: "l"(p), "r"(v) : "memory");
}
__device__ __forceinline__ void barn(int id, int cnt) {
    asm volatile("bar.sync %0, %1;" :: "r"(id), "r"(cnt) : "memory");
}

// ============================================================================
// Prep: fp16-convert act / inp / W_ih; reset all sync state.
// ============================================================================
__global__ void prep_kernel(const float* __restrict__ act,
                            const float* __restrict__ inp,
                            const float* __restrict__ Wih) {
    if (blockIdx.x == 0 && threadIdx.x == 0) {
        g_bar_count = 0; g_bar_gen = 0; g_tile_ctr = 0; g_inp_done = 0;
        for (int i = 0; i < Lt; i++) g_l_cnt[i] = 0;
    }
    const size_t NW = (size_t)Gd * 1024 / 8;
    const size_t NA = (size_t)Lt * Bt * KA / 8;
    const size_t NI = (size_t)Bt * KA / 8;
    const size_t total = NW + NA + NI;
    for (size_t i = (size_t)blockIdx.x * blockDim.x + threadIdx.x; i < total;
         i += (size_t)gridDim.x * blockDim.x) {
        const float4* s; uint4* d;
        if (i < NW)           { s = (const float4*)Wih + 2 * i;            d = (uint4*)g_wih_h + i; }
        else if (i < NW + NA) { s = (const float4*)act + 2 * (i - NW);     d = (uint4*)g_act_h + (i - NW); }
        else                  { s = (const float4*)inp + 2 * (i - NW - NA); d = (uint4*)g_inp_h + (i - NW - NA); }
        float4 v0 = s[0], v1 = s[1];
        uint4 o;
        o.x = h2u(__floats2half2_rn(v0.x, v0.y));
        o.y = h2u(__floats2half2_rn(v0.z, v0.w));
        o.z = h2u(__floats2half2_rn(v1.x, v1.y));
        o.w = h2u(__floats2half2_rn(v1.z, v1.w));
        *d = o;
    }
}

// ============================================================================
// FUSED persistent kernel: 128 CTAs x 384 threads.
//   warps 0-7  : LSTM recurrence (R14 warp-private pipelines, 3-deep rings)
//   warps 8-11 : GEMM producer group — 128x64 tiles from atomic work queue
//                (ids 0..63 = inp tiles -> g_gx_inp+bias; 64.. = act tiles,
//                ascending l), per-l readiness via red.release counters.
// Named barriers: bar1 = recurrence (256 thr), bar2 = producers (128 thr).
// ============================================================================
constexpr int FTHR = 384;
constexpr int WS_B = 64 * 1024;                 // W tiles
constexpr int WSLOT_B = 4096;                   // 16 rows x 128 cols fp16
constexpr int RING_B = 8 * 3 * WSLOT_B;         // 96 KB recurrence rings
constexpr int PSTAGE_B = 8192 + 4096;           // A 8K + B 4K per stage
constexpr int PSTG_B = 3 * PSTAGE_B;            // 36 KB producer stages
constexpr int SMEMF = WS_B + RING_B + PSTG_B + 64;   // ~197 KB
constexpr unsigned N_TILES = 64u + 128u * 64u;  // 8256

__global__ void __launch_bounds__(FTHR, 1) fused_kernel(
    const float* __restrict__ h0, const float* __restrict__ c0in,
    const float* __restrict__ Whh, const float* __restrict__ bih,
    const float* __restrict__ bhh, float* __restrict__ out, int out_size)
{
    extern __shared__ char sm2[];
    const uint32_t sW = s2u(sm2);
    const uint32_t sRing = sW + WS_B;
    const uint32_t sP = sRing + RING_B;
    unsigned* idslot = (unsigned*)(sm2 + WS_B + RING_B + PSTG_B);

    const int tid = threadIdx.x, lane = tid & 31, warp = tid >> 5;
    const int cta = blockIdx.x;
    const int g = lane >> 3, l7 = lane & 7;

    if (warp >= 8) {
        // ==================== PRODUCER PATH (warps 8-11) ====================
        const int ptid = tid - 256;          // 0..127
        const int pw = warp - 8;             // 0..3

        for (;;) {
            if (ptid == 0) *idslot = atomicAdd(&g_tile_ctr, 1u);
            barn(2, 128);
            unsigned id = *idslot;
            if (id >= N_TILES) break;

            const bool isInp = (id < 64u);
            const int y  = isInp ? 0 : (int)((id - 64u) >> 6);
            const int xi = isInp ? (int)id : (int)((id - 64u) & 63u);
            const int bn = xi * 64;
            const __half* Ab = isInp ? g_inp_h : g_act_h + (size_t)y * 128 * KA;
            const __half* Bb = g_wih_h + (size_t)bn * 1024 + (isInp ? 0 : 512);
            float* Cb = isInp ? g_gx_inp : g_gx_act + (size_t)y * 128 * Gd;

            auto pstage = [&](int kb) {
                if (kb < 16) {
                    uint32_t st = sP + (uint32_t)(kb % 3) * PSTAGE_B;
                    #pragma unroll
                    for (int j = 0; j < 4; j++) {
                        int idx = j * 128 + ptid;
                        int r = idx >> 2, c = idx & 3;
                        uint32_t off = (uint32_t)(((r >> 3) * 4 + c) * 128
                                     + (((r & 7) ^ c) * 16));
                        cpa16(st + off, Ab + (size_t)r * KA + kb * 32 + c * 8);
                    }
                    #pragma unroll
                    for (int j = 0; j < 2; j++) {
                        int idx = j * 128 + ptid;
                        int r = idx >> 2, c = idx & 3;
                        uint32_t off = (uint32_t)(((r >> 3) * 4 + c) * 128
                                     + (((r & 7) ^ c) * 16));
                        cpa16(st + 8192 + off, Bb + (size_t)r * 1024 + kb * 32 + c * 8);
                    }
                }
                cpcommit();
            };

            pstage(0); pstage(1);

            float acc[2][8][4];
            #pragma unroll
            for (int i = 0; i < 2; i++)
                #pragma unroll
                for (int j = 0; j < 8; j++)
                    #pragma unroll
                    for (int k = 0; k < 4; k++) acc[i][j][k] = 0.0f;

            for (int kb = 0; kb < 16; kb++) {
                cpwait<1>(); barn(2, 128);
                pstage(kb + 2);
                const uint32_t stA = sP + (uint32_t)(kb % 3) * PSTAGE_B;
                const uint32_t stB = stA + 8192;

                #pragma unroll
                for (int kc = 0; kc < 2; kc++) {
                    uint32_t a[2][4];
                    #pragma unroll
                    for (int tm = 0; tm < 2; tm++) {
                        int rt = pw * 4 + tm * 2 + (g & 1);
                        int ct = kc * 2 + (g >> 1);
                        ldsm4(a[tm][0], a[tm][1], a[tm][2], a[tm][3],
                              stA + (uint32_t)((rt * 4 + ct) * 128 + ((l7 ^ ct) * 16)));
                    }
                    #pragma unroll
                    for (int j = 0; j < 4; j++) {
                        int nt = 2 * j + (g >> 1);
                        int ct = kc * 2 + (g & 1);
                        uint32_t b0, b1, b2, b3;
                        ldsm4(b0, b1, b2, b3,
                              stB + (uint32_t)((nt * 4 + ct) * 128 + ((l7 ^ ct) * 16)));
                        mma16(acc[0][2 * j],     a[0], b0, b1);
                        mma16(acc[0][2 * j + 1], a[0], b2, b3);
                        mma16(acc[1][2 * j],     a[1], b0, b1);
                        mma16(acc[1][2 * j + 1], a[1], b2, b3);
                    }
                }
            }
            cpwait<0>();

            #pragma unroll
            for (int tm = 0; tm < 2; tm++) {
                int rr = pw * 32 + tm * 16 + (lane >> 2);
                #pragma unroll
                for (int tn = 0; tn < 8; tn++) {
                    int cc = bn + tn * 8 + 2 * (lane & 3);
                    float bv0 = 0.0f, bv1 = 0.0f;
                    if (isInp) {
                        bv0 = bih[cc] + bhh[cc];
                        bv1 = bih[cc + 1] + bhh[cc + 1];
                    }
                    *(float2*)&Cb[(size_t)rr * Gd + cc] =
                        make_float2(acc[tm][tn][0] + bv0, acc[tm][tn][1] + bv1);
                    *(float2*)&Cb[(size_t)(rr + 8) * Gd + cc] =
                        make_float2(acc[tm][tn][2] + bv0, acc[tm][tn][3] + bv1);
                }
            }
            __threadfence();
            barn(2, 128);
            if (ptid == 0) {
                if (isInp) redrel(&g_inp_done, 1u);
                else       redrel(&g_l_cnt[y], 1u);
            }
            barn(2, 128);    // protect idslot rewrite
        }
        return;
    }

    // ==================== RECURRENCE PATH (warps 0-7) ====================
    const int ub  = cta * 8;
    const int u0  = ub + 2 * (lane & 3);
    const int b0  = warp * 16 + (lane >> 2);
    const int stag = cta & 7;

    // W_hh slice -> smem fp16, tile-native layout
    for (int i = tid; i < 32 * 128; i += 256) {
        int lr = i >> 7;
        int c  = i & 127;
        int gate = lr >> 3, unit = lr & 7;
        const float* src = Whh + (size_t)(gate * Hd + ub + unit) * Hd + c * 8;
        float4 v0 = *(const float4*)src;
        float4 v1 = *(const float4*)(src + 4);
        uint4 o;
        o.x = h2u(__floats2half2_rn(v0.x, v0.y));
        o.y = h2u(__floats2half2_rn(v0.z, v0.w));
        o.z = h2u(__floats2half2_rn(v1.x, v1.y));
        o.w = h2u(__floats2half2_rn(v1.z, v1.w));
        uint32_t off = (uint32_t)((gate * 128 + c) * 128 + ((unit ^ (c & 7)) * 16));
        *(uint4*)(sm2 + off) = o;
    }

    float creg[2][2];
    #pragma unroll
    for (int bs = 0; bs < 2; bs++) {
        int b = b0 + bs * 8;
        creg[bs][0] = c0in[(size_t)b * Hd + u0];
        creg[bs][1] = c0in[(size_t)b * Hd + u0 + 1];
    }

    // initial h (fp16) -> buffer 0
    for (int i = tid; i < Hd / 2; i += 256) {
        float2 v = *(const float2*)&h0[(size_t)cta * Hd + 2 * i];
        *(__half2*)&g_hbuf_h[0][cta * Hd + 2 * i] = __floats2half2_rn(v.x, v.y);
    }
    // one-time grid barrier + initial readiness (inp GEMM + l=0)
    barn(1, 256);
    if (tid == 0) {
        __threadfence();
        unsigned old = atomicAdd(&g_bar_count, 1u);
        if ((old + 1u) % gridDim.x == 0u) { __threadfence(); redrel(&g_bar_gen, 1u); }
        while (ldacq(&g_bar_gen) < 1u) { }
        while (ldacq(&g_inp_done) < 64u) { }
        while (ldacq(&g_l_cnt[0]) < 64u) { }
        __threadfence();
    }
    barn(1, 256);

    // t-invariant gate term (bias folded in by producer inp tiles)
    float2 gxi[4][2];
    #pragma unroll
    for (int q = 0; q < 4; q++)
        #pragma unroll
        for (int bs = 0; bs < 2; bs++) {
            int b = b0 + bs * 8;
            gxi[q][bs] = *(const float2*)&g_gx_inp[(size_t)b * Gd + q * Hd + u0];
        }

    // per-warp staging geometry: slot = 16 rows x 128 cols (4 KB), 3-deep ring
    const uint32_t wbase = sRing + (uint32_t)warp * (3 * WSLOT_B);
    const int srh = lane >> 4;
    const int sc = lane & 15;
    const int aro = ((g & 1) << 3) + l7;

    for (int t = 0; t < Lt; t++) {
        const __half* cur = g_hbuf_h[t & 1];
        __half* nxt = g_hbuf_h[(t + 1) & 1];

        float2 gxa[4][2];
        #pragma unroll
        for (int q = 0; q < 4; q++)
            #pragma unroll
            for (int bs = 0; bs < 2; bs++) {
                int b = b0 + bs * 8;
                gxa[q][bs] = *(const float2*)
                    &g_gx_act[((size_t)t * Bt + b) * Gd + q * Hd + u0];
            }

        float acc[4][4];
        #pragma unroll
        for (int q = 0; q < 4; q++)
            #pragma unroll
            for (int k = 0; k < 4; k++) acc[q][k] = 0.0f;

        auto stage = [&](int s) {
            if (s < 8) {
                int ks = (s + stag) & 7;
                uint32_t st = wbase + (uint32_t)(s % 3) * WSLOT_B;
                #pragma unroll
                for (int jj = 0; jj < 8; jj++) {
                    int r = jj * 2 + srh;
                    uint32_t off = (uint32_t)(r * 256 + ((sc ^ (r & 7)) * 16));
                    cpa16(st + off,
                          cur + (size_t)(warp * 16 + r) * Hd + ks * 128 + sc * 8);
                }
            }
            cpcommit();
        };

        stage(0); stage(1);

        for (int s = 0; s < 8; s++) {
            cpwait<1>();                    // own groups only — no block sync
            stage(s + 2);
            const int ks = (s + stag) & 7;
            const uint32_t st = wbase + (uint32_t)(s % 3) * WSLOT_B;

            #pragma unroll
            for (int kk = 0; kk < 8; kk++) {
                uint32_t a[4];
                {
                    int ct = kk * 2 + (g >> 1);
                    ldsm4(a[0], a[1], a[2], a[3],
                          st + (uint32_t)(aro * 256 + ((ct ^ (aro & 7)) * 16)));
                }
                #pragma unroll
                for (int p = 0; p < 2; p++) {
                    int gate = 2 * p + (g >> 1);
                    int gck = ks * 16 + kk * 2 + (g & 1);
                    uint32_t b0r, b1r, b2r, b3r;
                    ldsm4(b0r, b1r, b2r, b3r,
                          sW + (uint32_t)((gate * 128 + gck) * 128
                               + ((l7 ^ (gck & 7)) * 16)));
                    mma16(acc[2 * p],     a, b0r, b1r);
                    mma16(acc[2 * p + 1], a, b2r, b3r);
                }
            }
        }
        cpwait<0>();

        // cell update -> registers
        float hv[2][2], cv[2][2];
        #pragma unroll
        for (int bs = 0; bs < 2; bs++)
            #pragma unroll
            for (int us = 0; us < 2; us++) {
                int ci = bs * 2 + us;
                float gi = acc[0][ci] + (us ? gxa[0][bs].y : gxa[0][bs].x)
                                      + (us ? gxi[0][bs].y : gxi[0][bs].x);
                float gf = acc[1][ci] + (us ? gxa[1][bs].y : gxa[1][bs].x)
                                      + (us ? gxi[1][bs].y : gxi[1][bs].x);
                float gg = acc[2][ci] + (us ? gxa[2][bs].y : gxa[2][bs].x)
                                      + (us ? gxi[2][bs].y : gxi[2][bs].x);
                float go = acc[3][ci] + (us ? gxa[3][bs].y : gxa[3][bs].x)
                                      + (us ? gxi[3][bs].y : gxi[3][bs].x);
                float cn = sigm(gf) * creg[bs][us] + sigm(gi) * tanhf(gg);
                float hn = sigm(go) * tanhf(cn);
                creg[bs][us] = cn;
                hv[bs][us] = hn; cv[bs][us] = cn;
            }

        if (t + 1 < Lt) {
            // publish h, arrive; out stores ride the wait window; gate on
            // both the barrier and l_cnt[t+1] (act tiles for next step).
            #pragma unroll
            for (int bs = 0; bs < 2; bs++) {
                int b = b0 + bs * 8;
                *(__half2*)&nxt[b * Hd + u0] =
                    __floats2half2_rn(hv[bs][0], hv[bs][1]);
            }
            barn(1, 256);
            if (tid == 0) {
                __threadfence();
                unsigned old = atomicAdd(&g_bar_count, 1u);
                if ((old + 1u) % gridDim.x == 0u) {
                    __threadfence();
                    redrel(&g_bar_gen, 1u);
                }
            }
            #pragma unroll
            for (int bs = 0; bs < 2; bs++) {
                int b = b0 + bs * 8;
                size_t ob = (size_t)t * Bt * Hd + (size_t)b * Hd + u0;
                *(float2*)&out[ob] = make_float2(hv[bs][0], hv[bs][1]);
            }
            if (tid == 0) {
                while (ldacq(&g_bar_gen) < (unsigned)(t + 2)) { }
                while (ldacq(&g_l_cnt[t + 1]) < 64u) { }
            }
            barn(1, 256);
        } else {
            #pragma unroll
            for (int bs = 0; bs < 2; bs++) {
                int b = b0 + bs * 8;
                size_t ob = (size_t)t * Bt * Hd + (size_t)b * Hd + u0;
                *(float2*)&out[ob] = make_float2(hv[bs][0], hv[bs][1]);
                size_t HS = (size_t)Lt * Bt * Hd;
                if ((size_t)out_size >= HS + 2 * (size_t)Bt * Hd) {
                    *(float2*)&out[HS + (size_t)b * Hd + u0] =
                        make_float2(hv[bs][0], hv[bs][1]);
                    *(float2*)&out[HS + (size_t)Bt * Hd + (size_t)b * Hd + u0] =
                        make_float2(cv[bs][0], cv[bs][1]);
                }
            }
        }
    }
}

extern "C" void kernel_launch(void* const* d_in, const int* in_sizes, int n_in,
                              void* d_out, int out_size) {
    (void)in_sizes; (void)n_in;
    const float* act = (const float*)d_in[0];
    const float* inp = (const float*)d_in[1];
    const float* h0  = (const float*)d_in[2];
    const float* c0  = (const float*)d_in[3];
    const float* Wih = (const float*)d_in[4];
    const float* Whh = (const float*)d_in[5];
    const float* bih = (const float*)d_in[6];
    const float* bhh = (const float*)d_in[7];
    float* out = (float*)d_out;

    cudaFuncSetAttribute(fused_kernel,
                         cudaFuncAttributeMaxDynamicSharedMemorySize, SMEMF);

    prep_kernel<<<1024, 256>>>(act, inp, Wih);
    fused_kernel<<<128, FTHR, SMEMF>>>(h0, c0, Whh, bih, bhh, out, out_size);
}

// round 16
// speedup vs baseline: 1.0503x; 1.0503x over previous
#include <cuda_runtime.h>
#include <cuda_fp16.h>
#include <cstdint>

// Problem dims
constexpr int Lt = 128;
constexpr int Bt = 128;
constexpr int Hd = 1024;
constexpr int Gd = 4 * Hd;       // 4096
constexpr int KA = 512;          // K of both sub-GEMMs

// Static scratch
__device__ __align__(16) __half g_gx_act_h[(size_t)Lt * Bt * Gd]; // fp16 gates
__device__ float g_gx_inp[(size_t)Bt * Gd];          // input-side + biases (f32)
__device__ __align__(16) __half g_act_h[(size_t)Lt * Bt * KA];
__device__ __align__(16) __half g_inp_h[(size_t)Bt * KA];
__device__ __align__(16) __half g_wih_h[(size_t)Gd * 1024];
__device__ __align__(16) __half g_hbuf_h[2][Bt * Hd];
__device__ unsigned g_bar_l1[8 * 32];                // per-group arrive (line-spread)
__device__ unsigned g_bar_count;
__device__ unsigned g_bar_gen;

// ---------------------------------------------------------------- helpers
__device__ __forceinline__ uint32_t h2u(__half2 v) {
    __half2_raw r = *(__half2_raw*)&v;
    return (uint32_t)r.x | ((uint32_t)r.y << 16);
}
__device__ __forceinline__ void mma16(float* c, const uint32_t* a,
                                      uint32_t b0, uint32_t b1) {
    asm volatile(
        "mma.sync.aligned.m16n8k16.row.col.f32.f16.f16.f32 "
        "{%0,%1,%2,%3},{%4,%5,%6,%7},{%8,%9},{%0,%1,%2,%3};"
        : "+f"(c[0]), "+f"(c[1]), "+f"(c[2]), "+f"(c[3])
        : "r"(a[0]), "r"(a[1]), "r"(a[2]), "r"(a[3]), "r"(b0), "r"(b1));
}
__device__ __forceinline__ void ldsm4(uint32_t& d0, uint32_t& d1,
                                      uint32_t& d2, uint32_t& d3, uint32_t a) {
    asm volatile("ldmatrix.sync.aligned.m8n8.x4.shared.b16 {%0,%1,%2,%3}, [%4];"
                 : "=r"(d0), "=r"(d1), "=r"(d2), "=r"(d3) : "r"(a));
}
__device__ __forceinline__ void cpa16(uint32_t d, const void* s) {
    asm volatile("cp.async.cg.shared.global [%0], [%1], 16;" :: "r"(d), "l"(s));
}
__device__ __forceinline__ void cpcommit() { asm volatile("cp.async.commit_group;"); }
template<int N> __device__ __forceinline__ void cpwait() {
    asm volatile("cp.async.wait_group %0;" :: "n"(N));
}
__device__ __forceinline__ uint32_t s2u(const void* p) {
    return (uint32_t)__cvta_generic_to_shared(p);
}
__device__ __forceinline__ float sigm(float x) { return 1.0f / (1.0f + expf(-x)); }
__device__ __forceinline__ unsigned ldacq(const unsigned* p) {
    unsigned v;
    asm volatile("ld.acquire.gpu.global.u32 %0, [%1];" : "=r"(v) : "l"(p) : "memory");
    return v;
}
__device__ __forceinline__ void redrel(unsigned* p, unsigned v) {
    asm volatile("red.release.gpu.global.add.u32 [%0], %1;" :: "l"(p), "r"(v) : "memory");
}

// hierarchical arrive: 16-CTA groups on spread lines -> master -> gen release
__device__ __forceinline__ void gbar_arrive(int cta) {
    __threadfence();
    unsigned o1 = atomicAdd(&g_bar_l1[(cta >> 4) * 32], 1u);
    if ((o1 & 15u) == 15u) {
        unsigned o2 = atomicAdd(&g_bar_count, 1u);
        if ((o2 & 7u) == 7u) { __threadfence(); redrel(&g_bar_gen, 1u); }
    }
}

// ============================================================================
// Prep: fp16-convert act / inp / W_ih; reset sync counters.
// ============================================================================
__global__ void prep_kernel(const float* __restrict__ act,
                            const float* __restrict__ inp,
                            const float* __restrict__ Wih) {
    if (blockIdx.x == 0 && threadIdx.x == 0) {
        g_bar_count = 0; g_bar_gen = 0;
        for (int i = 0; i < 8; i++) g_bar_l1[i * 32] = 0;
    }
    const size_t NW = (size_t)Gd * 1024 / 8;      // 8-elem groups
    const size_t NA = (size_t)Lt * Bt * KA / 8;
    const size_t NI = (size_t)Bt * KA / 8;
    const size_t total = NW + NA + NI;
    for (size_t i = (size_t)blockIdx.x * blockDim.x + threadIdx.x; i < total;
         i += (size_t)gridDim.x * blockDim.x) {
        const float4* s; uint4* d;
        if (i < NW)           { s = (const float4*)Wih + 2 * i;            d = (uint4*)g_wih_h + i; }
        else if (i < NW + NA) { s = (const float4*)act + 2 * (i - NW);     d = (uint4*)g_act_h + (i - NW); }
        else                  { s = (const float4*)inp + 2 * (i - NW - NA); d = (uint4*)g_inp_h + (i - NW - NA); }
        float4 v0 = s[0], v1 = s[1];
        uint4 o;
        o.x = h2u(__floats2half2_rn(v0.x, v0.y));
        o.y = h2u(__floats2half2_rn(v0.z, v0.w));
        o.z = h2u(__floats2half2_rn(v1.x, v1.y));
        o.w = h2u(__floats2half2_rn(v1.z, v1.w));
        *d = o;
    }
}

// ============================================================================
// Phase 1: fp16 m16n8k16 GEMM (R10 coalesced staging + bias fold).
// Act tiles now store gx in FP16 (halves epilogue DRAM traffic).
// ============================================================================
constexpr int P1_STG = 4;
constexpr int P1_STAGE_B = 2 * 128 * 32 * 2;   // A 8KB + B 8KB = 16 KB
constexpr int P1_SMEM = P1_STG * P1_STAGE_B;   // 64 KB

__global__ void __launch_bounds__(256, 2) gemm_x_h(const float* __restrict__ bih,
                                                   const float* __restrict__ bhh) {
    extern __shared__ char sm1[];
    const uint32_t sBase = s2u(sm1);

    const int tid = threadIdx.x, lane = tid & 31, warp = tid >> 5;
    const int wm = warp & 3, wn = warp >> 2;
    const bool isInp = (blockIdx.y == 128);
    const int bm = isInp ? 0 : blockIdx.y * 128;
    const int bn = blockIdx.x * 128;
    const __half* Ab = isInp ? g_inp_h : g_act_h + (size_t)bm * KA;
    const __half* Bb = g_wih_h + (size_t)bn * 1024 + (isInp ? 0 : 512);
    float* CbF = g_gx_inp;
    __half* CbH = g_gx_act_h + (size_t)bm * Gd;

    const int c4 = lane & 3;
    const int r8 = lane >> 2;

    auto loadblk = [&](int kb) {
        if (kb < 16) {
            uint32_t st = sBase + (uint32_t)(kb & 3) * P1_STAGE_B;
            #pragma unroll
            for (int j = 0; j < 2; j++) {
                int r = (warp * 2 + j) * 8 + r8;
                uint32_t off = (uint32_t)(((r >> 3) * 4 + c4) * 128
                             + (((r & 7) ^ c4) * 16));
                cpa16(st + off, Ab + (size_t)r * KA + kb * 32 + c4 * 8);
                cpa16(st + 8192 + off, Bb + (size_t)r * 1024 + kb * 32 + c4 * 8);
            }
        }
        cpcommit();
    };

    loadblk(0); loadblk(1); loadblk(2);

    float acc[2][8][4];
    #pragma unroll
    for (int i = 0; i < 2; i++)
        #pragma unroll
        for (int j = 0; j < 8; j++)
            #pragma unroll
            for (int k = 0; k < 4; k++) acc[i][j][k] = 0.0f;

    const int g = lane >> 3;
    const int l7 = lane & 7;

    for (int kb = 0; kb < 16; kb++) {
        cpwait<2>(); __syncthreads();
        loadblk(kb + 3);
        const uint32_t stA = sBase + (uint32_t)(kb & 3) * P1_STAGE_B;
        const uint32_t stB = stA + 8192;

        #pragma unroll
        for (int kc = 0; kc < 2; kc++) {
            uint32_t a[2][4];
            #pragma unroll
            for (int tm = 0; tm < 2; tm++) {
                int rt = wm * 4 + tm * 2 + (g & 1);
                int ct = kc * 2 + (g >> 1);
                ldsm4(a[tm][0], a[tm][1], a[tm][2], a[tm][3],
                      stA + (uint32_t)((rt * 4 + ct) * 128 + ((l7 ^ ct) * 16)));
            }
            #pragma unroll
            for (int j = 0; j < 4; j++) {
                int nt = wn * 8 + 2 * j + (g >> 1);
                int ct = kc * 2 + (g & 1);
                uint32_t b0, b1, b2, b3;
                ldsm4(b0, b1, b2, b3,
                      stB + (uint32_t)((nt * 4 + ct) * 128 + ((l7 ^ ct) * 16)));
                mma16(acc[0][2 * j],     a[0], b0, b1);
                mma16(acc[0][2 * j + 1], a[0], b2, b3);
                mma16(acc[1][2 * j],     a[1], b0, b1);
                mma16(acc[1][2 * j + 1], a[1], b2, b3);
            }
        }
    }

    #pragma unroll
    for (int tm = 0; tm < 2; tm++) {
        int rr = wm * 32 + tm * 16 + (lane >> 2);
        #pragma unroll
        for (int tn = 0; tn < 8; tn++) {
            int cc = bn + wn * 64 + tn * 8 + 2 * (lane & 3);
            if (isInp) {
                float bv0 = bih[cc] + bhh[cc];
                float bv1 = bih[cc + 1] + bhh[cc + 1];
                *(float2*)&CbF[(size_t)rr * Gd + cc] =
                    make_float2(acc[tm][tn][0] + bv0, acc[tm][tn][1] + bv1);
                *(float2*)&CbF[(size_t)(rr + 8) * Gd + cc] =
                    make_float2(acc[tm][tn][2] + bv0, acc[tm][tn][3] + bv1);
            } else {
                *(__half2*)&CbH[(size_t)rr * Gd + cc] =
                    __floats2half2_rn(acc[tm][tn][0], acc[tm][tn][1]);
                *(__half2*)&CbH[(size_t)(rr + 8) * Gd + cc] =
                    __floats2half2_rn(acc[tm][tn][2], acc[tm][tn][3]);
            }
        }
    }
}

// ============================================================================
// Phase 2: persistent LSTM, 128 CTAs, WARP-PRIVATE pipelines (R14) +
// hierarchical grid barrier + fp16 gxa reads.
// ============================================================================
constexpr int NTHR = 256;
constexpr int WS_B = 32 * 1024 * 2;             // 64 KB W tiles
constexpr int WSLOT_B = 16 * 256;               // 4 KB per warp per slot
constexpr int SMEM2 = WS_B + 8 * 4 * WSLOT_B;   // 192 KB

__global__ void __launch_bounds__(NTHR, 1) lstm_seq_kernel(
    const float* __restrict__ h0, const float* __restrict__ c0in,
    const float* __restrict__ Whh, float* __restrict__ out, int out_size)
{
    extern __shared__ char sm2[];
    const uint32_t sW = s2u(sm2);
    const uint32_t sSt = sW + WS_B;

    const int tid = threadIdx.x, lane = tid & 31, warp = tid >> 5;
    const int cta = blockIdx.x;
    const int ub  = cta * 8;
    const int u0  = ub + 2 * (lane & 3);
    const int b0  = warp * 16 + (lane >> 2);
    const int stag = cta & 7;

    // --- W_hh slice -> smem fp16, tile-native layout
    for (int i = tid; i < 32 * 128; i += NTHR) {
        int lr = i >> 7;
        int c  = i & 127;
        int gate = lr >> 3, unit = lr & 7;
        const float* src = Whh + (size_t)(gate * Hd + ub + unit) * Hd + c * 8;
        float4 v0 = *(const float4*)src;
        float4 v1 = *(const float4*)(src + 4);
        uint4 o;
        o.x = h2u(__floats2half2_rn(v0.x, v0.y));
        o.y = h2u(__floats2half2_rn(v0.z, v0.w));
        o.z = h2u(__floats2half2_rn(v1.x, v1.y));
        o.w = h2u(__floats2half2_rn(v1.z, v1.w));
        uint32_t off = (uint32_t)((gate * 128 + c) * 128 + ((unit ^ (c & 7)) * 16));
        *(uint4*)(sm2 + off) = o;
    }

    // t-invariant gate term (bias folded in by phase 1)
    float2 gxi[4][2];
    #pragma unroll
    for (int q = 0; q < 4; q++)
        #pragma unroll
        for (int bs = 0; bs < 2; bs++) {
            int b = b0 + bs * 8;
            gxi[q][bs] = *(const float2*)&g_gx_inp[(size_t)b * Gd + q * Hd + u0];
        }

    float creg[2][2];
    #pragma unroll
    for (int bs = 0; bs < 2; bs++) {
        int b = b0 + bs * 8;
        creg[bs][0] = c0in[(size_t)b * Hd + u0];
        creg[bs][1] = c0in[(size_t)b * Hd + u0 + 1];
    }

    // initial h (fp16) -> buffer 0
    for (int i = tid; i < Hd / 2; i += NTHR) {
        float2 v = *(const float2*)&h0[(size_t)cta * Hd + 2 * i];
        *(__half2*)&g_hbuf_h[0][cta * Hd + 2 * i] = __floats2half2_rn(v.x, v.y);
    }
    // one-time full barrier
    __syncthreads();
    if (tid == 0) {
        gbar_arrive(cta);
        while (ldacq(&g_bar_gen) < 1u) { }
        __threadfence();
    }
    __syncthreads();

    // per-warp staging geometry (R14)
    const uint32_t wbase = sSt + (uint32_t)warp * (4 * WSLOT_B);
    const int srh = lane >> 4;
    const int sc = lane & 15;
    const int g = lane >> 3, l7 = lane & 7;
    const int aro = ((g & 1) << 3) + l7;

    for (int t = 0; t < Lt; t++) {
        const __half* cur = g_hbuf_h[t & 1];
        __half* nxt = g_hbuf_h[(t + 1) & 1];

        float2 gxa[4][2];
        #pragma unroll
        for (int q = 0; q < 4; q++)
            #pragma unroll
            for (int bs = 0; bs < 2; bs++) {
                int b = b0 + bs * 8;
                gxa[q][bs] = __half22float2(*(const __half2*)
                    &g_gx_act_h[((size_t)t * Bt + b) * Gd + q * Hd + u0]);
            }

        float acc[4][4];
        #pragma unroll
        for (int q = 0; q < 4; q++)
            #pragma unroll
            for (int k = 0; k < 4; k++) acc[q][k] = 0.0f;

        auto stage = [&](int s) {
            if (s < 8) {
                int ks = (s + stag) & 7;
                uint32_t st = wbase + (uint32_t)(s & 3) * WSLOT_B;
                #pragma unroll
                for (int jj = 0; jj < 8; jj++) {
                    int r = jj * 2 + srh;
                    uint32_t off = (uint32_t)(r * 256 + ((sc ^ (r & 7)) * 16));
                    cpa16(st + off,
                          cur + (size_t)(warp * 16 + r) * Hd + ks * 128 + sc * 8);
                }
            }
            cpcommit();
        };

        stage(0); stage(1); stage(2);

        for (int s = 0; s < 8; s++) {
            cpwait<2>();                    // own groups only — no block sync
            stage(s + 3);
            const int ks = (s + stag) & 7;
            const uint32_t st = wbase + (uint32_t)(s & 3) * WSLOT_B;

            #pragma unroll
            for (int kk = 0; kk < 8; kk++) {
                uint32_t a[4];
                {
                    int ct = kk * 2 + (g >> 1);
                    ldsm4(a[0], a[1], a[2], a[3],
                          st + (uint32_t)(aro * 256 + ((ct ^ (aro & 7)) * 16)));
                }
                #pragma unroll
                for (int p = 0; p < 2; p++) {
                    int gate = 2 * p + (g >> 1);
                    int gck = ks * 16 + kk * 2 + (g & 1);
                    uint32_t b0r, b1r, b2r, b3r;
                    ldsm4(b0r, b1r, b2r, b3r,
                          sW + (uint32_t)((gate * 128 + gck) * 128
                               + ((l7 ^ (gck & 7)) * 16)));
                    mma16(acc[2 * p],     a, b0r, b1r);
                    mma16(acc[2 * p + 1], a, b2r, b3r);
                }
            }
        }
        cpwait<0>();

        // cell update -> registers
        float hv[2][2], cv[2][2];
        #pragma unroll
        for (int bs = 0; bs < 2; bs++)
            #pragma unroll
            for (int us = 0; us < 2; us++) {
                int ci = bs * 2 + us;
                float gi = acc[0][ci] + (us ? gxa[0][bs].y : gxa[0][bs].x)
                                      + (us ? gxi[0][bs].y : gxi[0][bs].x);
                float gf = acc[1][ci] + (us ? gxa[1][bs].y : gxa[1][bs].x)
                                      + (us ? gxi[1][bs].y : gxi[1][bs].x);
                float gg = acc[2][ci] + (us ? gxa[2][bs].y : gxa[2][bs].x)
                                      + (us ? gxi[2][bs].y : gxi[2][bs].x);
                float go = acc[3][ci] + (us ? gxa[3][bs].y : gxa[3][bs].x)
                                      + (us ? gxi[3][bs].y : gxi[3][bs].x);
                float cn = sigm(gf) * creg[bs][us] + sigm(gi) * tanhf(gg);
                float hn = sigm(go) * tanhf(cn);
                creg[bs][us] = cn;
                hv[bs][us] = hn; cv[bs][us] = cn;
            }

        if (t + 1 < Lt) {
            // publish h first (2KB, L2), then hierarchical arrive
            #pragma unroll
            for (int bs = 0; bs < 2; bs++) {
                int b = b0 + bs * 8;
                *(__half2*)&nxt[b * Hd + u0] =
                    __floats2half2_rn(hv[bs][0], hv[bs][1]);
            }
            __syncthreads();
            if (tid == 0) gbar_arrive(cta);
            // out stores ride inside the wait window
            #pragma unroll
            for (int bs = 0; bs < 2; bs++) {
                int b = b0 + bs * 8;
                size_t ob = (size_t)t * Bt * Hd + (size_t)b * Hd + u0;
                *(float2*)&out[ob] = make_float2(hv[bs][0], hv[bs][1]);
            }
            if (tid == 0) {
                while (ldacq(&g_bar_gen) < (unsigned)(t + 2)) { }
            }
            __syncthreads();
        } else {
            #pragma unroll
            for (int bs = 0; bs < 2; bs++) {
                int b = b0 + bs * 8;
                size_t ob = (size_t)t * Bt * Hd + (size_t)b * Hd + u0;
                *(float2*)&out[ob] = make_float2(hv[bs][0], hv[bs][1]);
                size_t HS = (size_t)Lt * Bt * Hd;
                if ((size_t)out_size >= HS + 2 * (size_t)Bt * Hd) {
                    *(float2*)&out[HS + (size_t)b * Hd + u0] =
                        make_float2(hv[bs][0], hv[bs][1]);
                    *(float2*)&out[HS + (size_t)Bt * Hd + (size_t)b * Hd + u0] =
                        make_float2(cv[bs][0], cv[bs][1]);
                }
            }
        }
    }
}

extern "C" void kernel_launch(void* const* d_in, const int* in_sizes, int n_in,
                              void* d_out, int out_size) {
    (void)in_sizes; (void)n_in;
    const float* act = (const float*)d_in[0];
    const float* inp = (const float*)d_in[1];
    const float* h0  = (const float*)d_in[2];
    const float* c0  = (const float*)d_in[3];
    const float* Wih = (const float*)d_in[4];
    const float* Whh = (const float*)d_in[5];
    const float* bih = (const float*)d_in[6];
    const float* bhh = (const float*)d_in[7];
    float* out = (float*)d_out;

    cudaFuncSetAttribute(gemm_x_h,
                         cudaFuncAttributeMaxDynamicSharedMemorySize, P1_SMEM);
    cudaFuncSetAttribute(lstm_seq_kernel,
                         cudaFuncAttributeMaxDynamicSharedMemorySize, SMEM2);

    prep_kernel<<<1024, 256>>>(act, inp, Wih);
    gemm_x_h<<<dim3(32, 129), 256, P1_SMEM>>>(bih, bhh);
    lstm_seq_kernel<<<128, NTHR, SMEM2>>>(h0, c0, Whh, out, out_size);
}